// round 14
// baseline (speedup 1.0000x reference)
#include <cuda_runtime.h>

// adapt_smoothing: out[b,s,f] = sum_{l=0..24} w[l] * x[b, max(s+l-24,0), f]
// x: [B=32, S=4096, F=512] fp32, w: [K=25] fp32.
//
// v12 = v5 per-thread code with 256-thread blocks owning FULL feature rows.
// v9-v11 established: ptxas codegen at <106 regs collapses per-warp memory
// rate (96-reg variants all ~115us); the fast codegen appears at budget 128
// with 128-thr blocks. (256,2) has the identical 128-reg budget, so codegen
// should match, occupancy stays 16 warps/SM -- the CHANGE is access pattern:
// grid.x=1 means each CTA reads x[b, t..t+4, :] = 10KB fully CONTIGUOUS per
// cp.async batch (v5's grid.x=2 produced 1KB pieces at 2KB stride), and the
// store stream is sequential too. smem 80KB/CTA via dynamic shared memory.
// Pipeline unchanged: cp.async FIFO 8B/thread/row, DEPTH=6 of NSB=8 slots,
// empty-group drain, LDS.64 -> statically-indexed 25-slot ring, packed
// fma.rn.f32x2, skip-issue overhang, no barriers.

#define B_DIM  32
#define S_DIM  4096
#define F_DIM  512
#define K_DIM  25
#define P_DIM  (F_DIM / 2)    // 256 u64 columns total
#define HALF_P 256            // u64 columns per block = ALL columns
#define S_TILE 200            // outputs per chunk (multiple of 25)
#define N_CHUNK 21            // grid = 1*21*32 = 672
#define ROWS   (S_TILE + K_DIM)   // 225 staged rows per chunk
#define BATCH  5
#define NBATCH (ROWS / BATCH) // 45
#define NSB    8              // smem ring slots (in batches)
#define DEPTH  6              // batches in flight (30 rows/thread)
#define SMEM_BYTES (NSB * BATCH * HALF_P * 8)   // 81920 B

typedef unsigned long long u64;

__device__ __forceinline__ u64 pack2(float v) {
    union { float f[2]; u64 u; } c;
    c.f[0] = v; c.f[1] = v;
    return c.u;
}
__device__ __forceinline__ u64 fma2(u64 a, u64 b, u64 c) {
    u64 d; asm("fma.rn.f32x2 %0, %1, %2, %3;" : "=l"(d) : "l"(a), "l"(b), "l"(c)); return d;
}
__device__ __forceinline__ u64 add2(u64 a, u64 b) {
    u64 d; asm("add.rn.f32x2 %0, %1, %2;" : "=l"(d) : "l"(a), "l"(b)); return d;
}

__global__ __launch_bounds__(HALF_P, 2) void adapt_smoothing_kernel(
    const float* __restrict__ x,
    const float* __restrict__ w,
    float* __restrict__ out)
{
    extern __shared__ u64 stage[];                // 80 KB dynamic

    const int tid = threadIdx.x;
    const int fp  = tid;                          // u64 column, 0..255
    const int s0  = blockIdx.y * S_TILE;          // multiple of 25
    const int bz  = blockIdx.z;

    const u64* __restrict__ xv = (const u64*)x;
    u64* __restrict__ ov = (u64*)out;
    const int boff = bz * (S_DIM * P_DIM) + fp;   // max ~33.5M, fits int

    // Packed broadcast weights (both f32 halves = w[l]).
    u64 pw[K_DIM];
#pragma unroll
    for (int l = 0; l < K_DIM; ++l) pw[l] = pack2(__ldg(&w[l]));

    // Producer: stage batch `bat` (5 rows, 8B per thread per row). Rows of a
    // batch are CONTIGUOUS in gmem (full 2KB rows, consecutive t).
    //  - t < 0       : clamp to row 0 (history edge padding).
    //  - t >= S_DIM  : skip the cp.async (outputs there are store-guarded).
    //  - bat >= NBATCH: commit an EMPTY group to keep the
    //                   "committed == bat + DEPTH" invariant in the drain.
    auto issue_batch = [&](int bat) {
        if (bat < NBATCH) {
            const int base_r = bat * BATCH;
            u64* dst = &stage[(bat & (NSB - 1)) * (BATCH * HALF_P) + tid];
#pragma unroll
            for (int rr = 0; rr < BATCH; ++rr) {
                int t = s0 - K_DIM + base_r + rr;           // row timestep
                if (t < S_DIM) {
                    t = t < 0 ? 0 : t;                      // history edge clamp
                    const u64* src = &xv[boff + t * P_DIM];
                    unsigned saddr = (unsigned)__cvta_generic_to_shared(dst + rr * HALF_P);
                    asm volatile("cp.async.ca.shared.global [%0], [%1], 8;\n"
                                 :: "r"(saddr), "l"(src));
                }
            }
        }
        asm volatile("cp.async.commit_group;\n");
    };

    // Prologue: DEPTH batches in flight.
#pragma unroll
    for (int bq = 0; bq < DEPTH; ++bq) issue_batch(bq);

    u64 ring[K_DIM];   // ring[t % 25] = x[b, t, col]

    for (int bb = 0; bb < NBATCH / 5; ++bb) {     // 9 outer iterations
#pragma unroll
        for (int sub = 0; sub < 5; ++sub) {       // 5 batches => 25 rows, static
            const int bat = bb * 5 + sub;

            // Groups committed == bat + DEPTH, so wait_group(DEPTH-1) proves
            // groups 0..bat are complete.
            asm volatile("cp.async.wait_group %0;\n" :: "n"(DEPTH - 1));

            // Refill (or empty-commit in the drain phase).
            issue_batch(bat + DEPTH);

            const u64* src = &stage[(bat & (NSB - 1)) * (BATCH * HALF_P) + tid];
#pragma unroll
            for (int rr = 0; rr < BATCH; ++rr) {
                const int p = sub * BATCH + rr;   // static 0..24 == r % 25
                const int r = bat * BATCH + rr;
                const int t = s0 - K_DIM + r;

                ring[p] = src[rr * HALF_P];       // LDS.64 (own bytes)

                if (r >= K_DIM && t < S_DIM) {
                    // out[t] = sum_l pw[l] (*) ring[(p+1+l) % 25]
                    u64 a0 = 0ULL, a1 = 0ULL, a2 = 0ULL, a3 = 0ULL;
#pragma unroll
                    for (int l = 0; l < K_DIM; l += 4) {
                        a0 = fma2(pw[l], ring[(p + 1 + l) % K_DIM], a0);
                        if (l + 1 < K_DIM) a1 = fma2(pw[l + 1], ring[(p + 2 + l) % K_DIM], a1);
                        if (l + 2 < K_DIM) a2 = fma2(pw[l + 2], ring[(p + 3 + l) % K_DIM], a2);
                        if (l + 3 < K_DIM) a3 = fma2(pw[l + 3], ring[(p + 4 + l) % K_DIM], a3);
                    }
                    ov[boff + t * P_DIM] = add2(add2(a0, a1), add2(a2, a3));
                }
            }
        }
    }
}

extern "C" void kernel_launch(void* const* d_in, const int* in_sizes, int n_in,
                              void* d_out, int out_size)
{
    const float* x = (const float*)d_in[0];
    const float* w = (const float*)d_in[1];
    float* out = (float*)d_out;

    // Opt into 80KB dynamic smem (host-side attribute set; not a stream op,
    // graph-capture safe, no allocation).
    cudaFuncSetAttribute(adapt_smoothing_kernel,
                         cudaFuncAttributeMaxDynamicSharedMemorySize, SMEM_BYTES);

    dim3 grid(P_DIM / HALF_P, N_CHUNK, B_DIM);    // (1, 21, 32) = 672
    dim3 block(HALF_P);
    adapt_smoothing_kernel<<<grid, block, SMEM_BYTES>>>(x, w, out);
}

// round 15
// speedup vs baseline: 1.5366x; 1.5366x over previous
#include <cuda_runtime.h>

// adapt_smoothing: out[b,s,f] = sum_{l=0..24} w[l] * x[b, max(s+l-24,0), f]
// x: [B=32, S=4096, F=512] fp32, w: [K=25] fp32.
//
// v13 = v5 (best, 94.7us) with the producer burst INTERLEAVED.
// Session laws: (1) regs >= ~106 or per-warp rate collapses; (2) achieved BW
// scales with independent CTA contexts/SM (4x128thr best; 2x256thr terrible);
// (3) traffic already at floor. Remaining leak = cross-CTA L1tex-queue
// contention from 5-wide cp.async bursts (documented spread mechanism:
// co-resident CTAs' front-batched LDGSTS collide in the per-SM L1tex FIFO).
// Change: issue ONE cp.async of batch bat+DEPTH per consumed row of batch
// bat (commit after the 5th) -> MLP_p1 ~1, same group-count invariant,
// byte-identical consumer. Everything else is exactly v5: 128thr, (128,4),
// S_TILE=200, DEPTH=6, NSB=8, grid (2,21,32)=1344, empty-group drain,
// static mod-25 register ring, packed fma.rn.f32x2, no barriers.

#define B_DIM  32
#define S_DIM  4096
#define F_DIM  512
#define K_DIM  25
#define P_DIM  (F_DIM / 2)    // 256 u64 columns total
#define HALF_P 128            // u64 columns per block
#define S_TILE 200            // outputs per chunk (multiple of 25)
#define N_CHUNK 21            // grid = 2*21*32 = 1344
#define ROWS   (S_TILE + K_DIM)   // 225 staged rows per chunk
#define BATCH  5
#define NBATCH (ROWS / BATCH) // 45
#define NSB    8              // smem ring slots (in batches)
#define DEPTH  6              // batches in flight (30 rows)

typedef unsigned long long u64;

__device__ __forceinline__ u64 pack2(float v) {
    union { float f[2]; u64 u; } c;
    c.f[0] = v; c.f[1] = v;
    return c.u;
}
__device__ __forceinline__ u64 fma2(u64 a, u64 b, u64 c) {
    u64 d; asm("fma.rn.f32x2 %0, %1, %2, %3;" : "=l"(d) : "l"(a), "l"(b), "l"(c)); return d;
}
__device__ __forceinline__ u64 add2(u64 a, u64 b) {
    u64 d; asm("add.rn.f32x2 %0, %1, %2;" : "=l"(d) : "l"(a), "l"(b)); return d;
}

__global__ __launch_bounds__(HALF_P, 4) void adapt_smoothing_kernel(
    const float* __restrict__ x,
    const float* __restrict__ w,
    float* __restrict__ out)
{
    __shared__ u64 stage[NSB * BATCH * HALF_P];   // 40 KB

    const int tid = threadIdx.x;
    const int fp  = blockIdx.x * HALF_P + tid;    // u64 column, 0..255
    const int s0  = blockIdx.y * S_TILE;          // multiple of 25
    const int bz  = blockIdx.z;

    const u64* __restrict__ xv = (const u64*)x;
    u64* __restrict__ ov = (u64*)out;
    const int boff = bz * (S_DIM * P_DIM) + fp;   // max ~33.5M, fits int

    // Packed broadcast weights (both f32 halves = w[l]).
    u64 pw[K_DIM];
#pragma unroll
    for (int l = 0; l < K_DIM; ++l) pw[l] = pack2(__ldg(&w[l]));

    // Issue ONE staged row (row rr of batch bat). Edge handling:
    //  - t < 0: clamp to row 0;  - t >= S_DIM: skip (outputs store-guarded).
    auto issue_row = [&](int bat, int rr) {
        if (bat < NBATCH) {
            int t = s0 - K_DIM + bat * BATCH + rr;
            if (t < S_DIM) {
                t = t < 0 ? 0 : t;
                u64* dst = &stage[(bat & (NSB - 1)) * (BATCH * HALF_P) + rr * HALF_P + tid];
                const u64* src = &xv[boff + t * P_DIM];
                unsigned saddr = (unsigned)__cvta_generic_to_shared(dst);
                asm volatile("cp.async.ca.shared.global [%0], [%1], 8;\n"
                             :: "r"(saddr), "l"(src));
            }
        }
    };

    // Prologue: DEPTH committed batches in flight.
#pragma unroll
    for (int bq = 0; bq < DEPTH; ++bq) {
#pragma unroll
        for (int rr = 0; rr < BATCH; ++rr) issue_row(bq, rr);
        asm volatile("cp.async.commit_group;\n");
    }

    u64 ring[K_DIM];   // ring[t % 25] = x[b, t, col]

    for (int bb = 0; bb < NBATCH / 5; ++bb) {     // 9 outer iterations
#pragma unroll
        for (int sub = 0; sub < 5; ++sub) {       // 5 batches => 25 rows, static
            const int bat = bb * 5 + sub;

            // Committed groups == bat + DEPTH here, so wait_group(DEPTH-1)
            // proves groups 0..bat are complete.
            asm volatile("cp.async.wait_group %0;\n" :: "n"(DEPTH - 1));

            const u64* src = &stage[(bat & (NSB - 1)) * (BATCH * HALF_P) + tid];
#pragma unroll
            for (int rr = 0; rr < BATCH; ++rr) {
                // Interleaved refill: one row of batch bat+DEPTH per consumed
                // row (smooths LDGSTS injection; kills the 5-wide burst).
                issue_row(bat + DEPTH, rr);

                const int p = sub * BATCH + rr;   // static 0..24 == r % 25
                const int r = bat * BATCH + rr;
                const int t = s0 - K_DIM + r;

                ring[p] = src[rr * HALF_P];       // LDS.64 (own bytes)

                if (r >= K_DIM && t < S_DIM) {
                    // out[t] = sum_l pw[l] (*) ring[(p+1+l) % 25]
                    u64 a0 = 0ULL, a1 = 0ULL, a2 = 0ULL, a3 = 0ULL;
#pragma unroll
                    for (int l = 0; l < K_DIM; l += 4) {
                        a0 = fma2(pw[l], ring[(p + 1 + l) % K_DIM], a0);
                        if (l + 1 < K_DIM) a1 = fma2(pw[l + 1], ring[(p + 2 + l) % K_DIM], a1);
                        if (l + 2 < K_DIM) a2 = fma2(pw[l + 2], ring[(p + 3 + l) % K_DIM], a2);
                        if (l + 3 < K_DIM) a3 = fma2(pw[l + 3], ring[(p + 4 + l) % K_DIM], a3);
                    }
                    ov[boff + t * P_DIM] = add2(add2(a0, a1), add2(a2, a3));
                }
            }
            // Close the group for batch bat+DEPTH (empty in the drain phase,
            // keeping the committed == bat+DEPTH invariant exact).
            asm volatile("cp.async.commit_group;\n");
        }
    }
}

extern "C" void kernel_launch(void* const* d_in, const int* in_sizes, int n_in,
                              void* d_out, int out_size)
{
    const float* x = (const float*)d_in[0];
    const float* w = (const float*)d_in[1];
    float* out = (float*)d_out;

    dim3 grid(P_DIM / HALF_P, N_CHUNK, B_DIM);    // (2, 21, 32) = 1344
    dim3 block(HALF_P);
    adapt_smoothing_kernel<<<grid, block>>>(x, w, out);
}

// round 16
// speedup vs baseline: 1.5499x; 1.0086x over previous
#include <cuda_runtime.h>

// adapt_smoothing: out[b,s,f] = sum_{l=0..24} w[l] * x[b, max(s+l-24,0), f]
// x: [B=32, S=4096, F=512] fp32, w: [K=25] fp32.
//
// v14: 16-byte cp.async.cg (L1-BYPASS) staging. All prior ~70%-DRAM variants
// shared one constant: 8B cp.async.ca, which must route through L1 and costs
// 8 LDGSTS/warp/row. This round halves LDGSTS count and skips L1 entirely:
// each 1KB staged row is covered by 64 threads x 16B (.cg minimum), rows
// split by parity across thread halves so all 4 warps produce. Cross-thread
// staging requires wait_group -> __syncthreads -> consume for visibility
// (one barrier per 5-row batch; slot-reuse WAR protected by >=2 intervening
// barriers since NSB=8 > DEPTH=6). Consumer identical to v5: LDS.64 ->
// statically-indexed 25-slot ring, packed fma.rn.f32x2, STG.64.
// Geometry = v5: 128thr, (128,4), S_TILE=200, grid (2,21,32)=1344.

#define B_DIM  32
#define S_DIM  4096
#define F_DIM  512
#define K_DIM  25
#define P_DIM  (F_DIM / 2)    // 256 u64 columns total
#define HALF_P 128            // u64 columns per block
#define S_TILE 200            // outputs per chunk (multiple of 25)
#define N_CHUNK 21            // grid = 2*21*32 = 1344
#define ROWS   (S_TILE + K_DIM)   // 225 staged rows per chunk
#define BATCH  5
#define NBATCH (ROWS / BATCH) // 45
#define NSB    8              // smem ring slots (in batches)
#define DEPTH  6              // batches in flight (30 rows)

typedef unsigned long long u64;

__device__ __forceinline__ u64 pack2(float v) {
    union { float f[2]; u64 u; } c;
    c.f[0] = v; c.f[1] = v;
    return c.u;
}
__device__ __forceinline__ u64 fma2(u64 a, u64 b, u64 c) {
    u64 d; asm("fma.rn.f32x2 %0, %1, %2, %3;" : "=l"(d) : "l"(a), "l"(b), "l"(c)); return d;
}
__device__ __forceinline__ u64 add2(u64 a, u64 b) {
    u64 d; asm("add.rn.f32x2 %0, %1, %2;" : "=l"(d) : "l"(a), "l"(b)); return d;
}

__global__ __launch_bounds__(HALF_P, 4) void adapt_smoothing_kernel(
    const float* __restrict__ x,
    const float* __restrict__ w,
    float* __restrict__ out)
{
    __shared__ u64 stage[NSB * BATCH * HALF_P];   // 40 KB

    const int tid  = threadIdx.x;
    const int fp   = blockIdx.x * HALF_P + tid;   // consumer u64 column
    const int s0   = blockIdx.y * S_TILE;         // multiple of 25
    const int bz   = blockIdx.z;

    // Producer mapping: thread covers 16B = u64 columns {2*(tid&63), +1} of
    // rows whose parity matches (tid>>6). All 4 warps issue.
    const int pcol = 2 * (tid & 63);              // column within block
    const int half = tid >> 6;                    // 0: even rows, 1: odd rows

    const u64* __restrict__ xv = (const u64*)x;
    u64* __restrict__ ov = (u64*)out;
    const int base   = bz * (S_DIM * P_DIM);
    const int boff   = base + fp;                           // consumer
    const int pboff  = base + blockIdx.x * HALF_P + pcol;   // producer

    // Packed broadcast weights (both f32 halves = w[l]).
    u64 pw[K_DIM];
#pragma unroll
    for (int l = 0; l < K_DIM; ++l) pw[l] = pack2(__ldg(&w[l]));

    // Producer: stage batch `bat`. Each thread issues its parity rows
    // (rows 0,2,4 for half=0; rows 1,3 for half=1) as one 16B cp.async.cg.
    //  - t < 0: clamp to row 0;  - t >= S_DIM: skip (outputs store-guarded).
    //  - bat >= NBATCH: empty commit keeps the group-count invariant.
    auto issue_batch = [&](int bat) {
        if (bat < NBATCH) {
            const int base_r = bat * BATCH;
            u64* slot = &stage[(bat & (NSB - 1)) * (BATCH * HALF_P) + pcol];
#pragma unroll
            for (int rr = 0; rr < BATCH; ++rr) {
                if ((rr & 1) == half) {
                    int t = s0 - K_DIM + base_r + rr;       // row timestep
                    if (t < S_DIM) {
                        t = t < 0 ? 0 : t;                  // history edge clamp
                        const u64* src = &xv[pboff + t * P_DIM];
                        unsigned saddr = (unsigned)__cvta_generic_to_shared(slot + rr * HALF_P);
                        asm volatile("cp.async.cg.shared.global [%0], [%1], 16;\n"
                                     :: "r"(saddr), "l"(src));
                    }
                }
            }
        }
        asm volatile("cp.async.commit_group;\n");
    };

    // Prologue: DEPTH batches in flight.
#pragma unroll
    for (int bq = 0; bq < DEPTH; ++bq) issue_batch(bq);

    u64 ring[K_DIM];   // ring[t % 25] = x[b, t, col]

    for (int bb = 0; bb < NBATCH / 5; ++bb) {     // 9 outer iterations
#pragma unroll
        for (int sub = 0; sub < 5; ++sub) {       // 5 batches => 25 rows, static
            const int bat = bb * 5 + sub;

            // Groups committed == bat + DEPTH, so wait_group(DEPTH-1) proves
            // this thread's groups 0..bat are complete; the barrier makes all
            // threads' completions (and their smem writes) visible CTA-wide.
            asm volatile("cp.async.wait_group %0;\n" :: "n"(DEPTH - 1));
            __syncthreads();

            // Refill slot (bat+DEPTH)&7 == (bat-2)&7: its previous contents
            // (batch bat-2) were consumed >= 2 barriers ago -- WAR safe.
            issue_batch(bat + DEPTH);

            const u64* src = &stage[(bat & (NSB - 1)) * (BATCH * HALF_P) + tid];
#pragma unroll
            for (int rr = 0; rr < BATCH; ++rr) {
                const int p = sub * BATCH + rr;   // static 0..24 == r % 25
                const int r = bat * BATCH + rr;
                const int t = s0 - K_DIM + r;

                ring[p] = src[rr * HALF_P];       // LDS.64

                if (r >= K_DIM && t < S_DIM) {
                    // out[t] = sum_l pw[l] (*) ring[(p+1+l) % 25]
                    u64 a0 = 0ULL, a1 = 0ULL, a2 = 0ULL, a3 = 0ULL;
#pragma unroll
                    for (int l = 0; l < K_DIM; l += 4) {
                        a0 = fma2(pw[l], ring[(p + 1 + l) % K_DIM], a0);
                        if (l + 1 < K_DIM) a1 = fma2(pw[l + 1], ring[(p + 2 + l) % K_DIM], a1);
                        if (l + 2 < K_DIM) a2 = fma2(pw[l + 2], ring[(p + 3 + l) % K_DIM], a2);
                        if (l + 3 < K_DIM) a3 = fma2(pw[l + 3], ring[(p + 4 + l) % K_DIM], a3);
                    }
                    ov[boff + t * P_DIM] = add2(add2(a0, a1), add2(a2, a3));
                }
            }
        }
    }
}

extern "C" void kernel_launch(void* const* d_in, const int* in_sizes, int n_in,
                              void* d_out, int out_size)
{
    const float* x = (const float*)d_in[0];
    const float* w = (const float*)d_in[1];
    float* out = (float*)d_out;

    dim3 grid(P_DIM / HALF_P, N_CHUNK, B_DIM);    // (2, 21, 32) = 1344
    dim3 block(HALF_P);
    adapt_smoothing_kernel<<<grid, block>>>(x, w, out);
}

// round 17
// speedup vs baseline: 1.5540x; 1.0027x over previous
#include <cuda_runtime.h>

// adapt_smoothing: out[b,s,f] = sum_{l=0..24} w[l] * x[b, max(s+l-24,0), f]
// x: [B=32, S=4096, F=512] fp32, w: [K=25] fp32.
//
// v15 = EXACT v5 (session best: 94.7us bench / 91.5us ncu) + streaming
// stores (st.global.cs.b64, evict-first). Eight structural variants all
// plateau at ~5.6TB/s => mixed read+write HBM ceiling, not SM-side. The one
// cheap untried lever: demote the 256MB write stream in L2 eviction order so
// the chunk-overlap read reuse (which keeps read traffic at floor) survives.
// Pipeline: cp.async.ca FIFO 8B/thread/row, DEPTH=6 of NSB=8 slots,
// empty-group drain, LDS.64 -> statically-indexed 25-slot register ring,
// packed fma.rn.f32x2, no barriers. 128thr, (128,4), grid (2,21,32)=1344.

#define B_DIM  32
#define S_DIM  4096
#define F_DIM  512
#define K_DIM  25
#define P_DIM  (F_DIM / 2)    // 256 u64 columns total
#define HALF_P 128            // u64 columns per block
#define S_TILE 200            // outputs per chunk (multiple of 25)
#define N_CHUNK 21            // grid = 2*21*32 = 1344
#define ROWS   (S_TILE + K_DIM)   // 225 staged rows per chunk
#define BATCH  5
#define NBATCH (ROWS / BATCH) // 45
#define NSB    8              // smem ring slots (in batches)
#define DEPTH  6              // batches in flight (30 rows)

typedef unsigned long long u64;

__device__ __forceinline__ u64 pack2(float v) {
    union { float f[2]; u64 u; } c;
    c.f[0] = v; c.f[1] = v;
    return c.u;
}
__device__ __forceinline__ u64 fma2(u64 a, u64 b, u64 c) {
    u64 d; asm("fma.rn.f32x2 %0, %1, %2, %3;" : "=l"(d) : "l"(a), "l"(b), "l"(c)); return d;
}
__device__ __forceinline__ u64 add2(u64 a, u64 b) {
    u64 d; asm("add.rn.f32x2 %0, %1, %2;" : "=l"(d) : "l"(a), "l"(b)); return d;
}
__device__ __forceinline__ void stg_cs(u64* p, u64 v) {
    asm volatile("st.global.cs.b64 [%0], %1;" :: "l"(p), "l"(v) : "memory");
}

__global__ __launch_bounds__(HALF_P, 4) void adapt_smoothing_kernel(
    const float* __restrict__ x,
    const float* __restrict__ w,
    float* __restrict__ out)
{
    __shared__ u64 stage[NSB * BATCH * HALF_P];   // 40 KB

    const int tid = threadIdx.x;
    const int fp  = blockIdx.x * HALF_P + tid;    // u64 column, 0..255
    const int s0  = blockIdx.y * S_TILE;          // multiple of 25
    const int bz  = blockIdx.z;

    const u64* __restrict__ xv = (const u64*)x;
    u64* __restrict__ ov = (u64*)out;
    const int boff = bz * (S_DIM * P_DIM) + fp;   // max ~33.5M, fits int

    // Packed broadcast weights (both f32 halves = w[l]).
    u64 pw[K_DIM];
#pragma unroll
    for (int l = 0; l < K_DIM; ++l) pw[l] = pack2(__ldg(&w[l]));

    // Producer: stage batch `bat` (5 rows, 8B per thread per row).
    //  - t clamped to [0, S_DIM-1] (edge padding / overhang redundancy).
    //  - bat >= NBATCH: commit an EMPTY group to keep the
    //                   "committed == bat + DEPTH" invariant in the drain.
    auto issue_batch = [&](int bat) {
        if (bat < NBATCH) {
            const int base_r = bat * BATCH;
            u64* dst = &stage[(bat & (NSB - 1)) * (BATCH * HALF_P) + tid];
#pragma unroll
            for (int rr = 0; rr < BATCH; ++rr) {
                int t = s0 - K_DIM + base_r + rr;               // row timestep
                t = t < 0 ? 0 : (t >= S_DIM ? S_DIM - 1 : t);   // edge clamp
                const u64* src = &xv[boff + t * P_DIM];
                unsigned saddr = (unsigned)__cvta_generic_to_shared(dst + rr * HALF_P);
                asm volatile("cp.async.ca.shared.global [%0], [%1], 8;\n"
                             :: "r"(saddr), "l"(src));
            }
        }
        asm volatile("cp.async.commit_group;\n");
    };

    // Prologue: DEPTH batches in flight.
#pragma unroll
    for (int bq = 0; bq < DEPTH; ++bq) issue_batch(bq);

    u64 ring[K_DIM];   // ring[t % 25] = x[b, t, col]

    for (int bb = 0; bb < NBATCH / 5; ++bb) {     // 9 outer iterations
#pragma unroll
        for (int sub = 0; sub < 5; ++sub) {       // 5 batches => 25 rows, static
            const int bat = bb * 5 + sub;

            // Groups committed == bat + DEPTH, so wait_group(DEPTH-1) proves
            // groups 0..bat are complete.
            asm volatile("cp.async.wait_group %0;\n" :: "n"(DEPTH - 1));

            // Refill (or empty-commit in the drain phase).
            issue_batch(bat + DEPTH);

            const u64* src = &stage[(bat & (NSB - 1)) * (BATCH * HALF_P) + tid];
#pragma unroll
            for (int rr = 0; rr < BATCH; ++rr) {
                const int p = sub * BATCH + rr;   // static 0..24 == r % 25
                const int r = bat * BATCH + rr;
                const int t = s0 - K_DIM + r;

                ring[p] = src[rr * HALF_P];       // LDS.64 (own bytes)

                if (r >= K_DIM && t < S_DIM) {
                    // out[t] = sum_l pw[l] (*) ring[(p+1+l) % 25]
                    u64 a0 = 0ULL, a1 = 0ULL, a2 = 0ULL, a3 = 0ULL;
#pragma unroll
                    for (int l = 0; l < K_DIM; l += 4) {
                        a0 = fma2(pw[l], ring[(p + 1 + l) % K_DIM], a0);
                        if (l + 1 < K_DIM) a1 = fma2(pw[l + 1], ring[(p + 2 + l) % K_DIM], a1);
                        if (l + 2 < K_DIM) a2 = fma2(pw[l + 2], ring[(p + 3 + l) % K_DIM], a2);
                        if (l + 3 < K_DIM) a3 = fma2(pw[l + 3], ring[(p + 4 + l) % K_DIM], a3);
                    }
                    stg_cs(&ov[boff + t * P_DIM], add2(add2(a0, a1), add2(a2, a3)));
                }
            }
        }
    }
}

extern "C" void kernel_launch(void* const* d_in, const int* in_sizes, int n_in,
                              void* d_out, int out_size)
{
    const float* x = (const float*)d_in[0];
    const float* w = (const float*)d_in[1];
    float* out = (float*)d_out;

    dim3 grid(P_DIM / HALF_P, N_CHUNK, B_DIM);    // (2, 21, 32) = 1344
    dim3 block(HALF_P);
    adapt_smoothing_kernel<<<grid, block>>>(x, w, out);
}